// round 1
// baseline (speedup 1.0000x reference)
#include <cuda_runtime.h>

#define N_ROWS 32768
#define D_DIM  2048
#define B_DIM  2048

// -------- device scratch (static, allowed) --------
__device__ float g_sumsq[N_ROWS];
__device__ float g_wa[N_ROWS];
__device__ float g_colsum[D_DIM];
__device__ int   g_active[N_ROWS];
__device__ int   g_count;
__device__ int   g_maxbits;
__device__ int   g_qbucket;
__device__ float g_scale;

// -------- init --------
__global__ void k_init() {
    g_count   = 0;
    g_maxbits = 0;
}

// -------- per-row: sum(w^2), sum(w*a), max over sumsq --------
__global__ __launch_bounds__(256) void k_rowstats(const float* __restrict__ W,
                                                  const float* __restrict__ a) {
    int row = blockIdx.x;
    int tid = threadIdx.x;
    const float4* wr = reinterpret_cast<const float4*>(W + (size_t)row * D_DIM);
    const float4* a4 = reinterpret_cast<const float4*>(a);

    float ss = 0.f, wa = 0.f;
#pragma unroll
    for (int i = 0; i < 2; i++) {
        int idx = tid + i * 256;            // 512 float4 per row
        float4 w  = wr[idx];
        float4 av = __ldg(&a4[idx]);
        ss += w.x * w.x + w.y * w.y + w.z * w.z + w.w * w.w;
        wa += w.x * av.x + w.y * av.y + w.z * av.z + w.w * av.w;
    }
    // warp reduce
    for (int o = 16; o; o >>= 1) {
        ss += __shfl_down_sync(0xFFFFFFFFu, ss, o);
        wa += __shfl_down_sync(0xFFFFFFFFu, wa, o);
    }
    __shared__ float sss[8], swa[8];
    int wid = tid >> 5, lane = tid & 31;
    if (lane == 0) { sss[wid] = ss; swa[wid] = wa; }
    __syncthreads();
    if (tid == 0) {
        double S = 0.0, A = 0.0;
#pragma unroll
        for (int i = 0; i < 8; i++) { S += sss[i]; A += swa[i]; }
        float Sf = (float)S;
        g_sumsq[row] = Sf;
        g_wa[row]    = (float)A;
        atomicMax(&g_maxbits, __float_as_int(Sf));   // sumsq > 0: int compare == float compare
    }
}

// -------- column sums of x --------
__global__ __launch_bounds__(256) void k_colsum(const float* __restrict__ x) {
    int d = blockIdx.x * 256 + threadIdx.x;
    float a0 = 0.f, a1 = 0.f, a2 = 0.f, a3 = 0.f;
    for (int b = 0; b < B_DIM; b += 4) {
        a0 += x[(size_t)(b + 0) * D_DIM + d];
        a1 += x[(size_t)(b + 1) * D_DIM + d];
        a2 += x[(size_t)(b + 2) * D_DIM + d];
        a3 += x[(size_t)(b + 3) * D_DIM + d];
    }
    g_colsum[d] = (float)(((double)a0 + a1) + ((double)a2 + a3));
}

// -------- q bucket + scale --------
__global__ __launch_bounds__(256) void k_qhash(const float* __restrict__ a) {
    __shared__ double s_n2[256], s_ca[256];
    int t = threadIdx.x;
    double n2 = 0.0, ca = 0.0;
    for (int d = t; d < D_DIM; d += 256) {
        float c = g_colsum[d];
        n2 += (double)c * (double)c;
        ca += (double)c * (double)a[d];
    }
    s_n2[t] = n2; s_ca[t] = ca;
    __syncthreads();
    for (int off = 128; off; off >>= 1) {
        if (t < off) { s_n2[t] += s_n2[t + off]; s_ca[t] += s_ca[t + off]; }
        __syncthreads();
    }
    if (t == 0) {
        float nrm = sqrtf((float)s_n2[0]);       // ||colsum||; /B cancels in q = ave/||ave||
        float qd  = (float)s_ca[0] / nrm;        // dot(q, a[:D])
        float tail = a[D_DIM] + a[D_DIM + 1] + a[D_DIM + 2] + a[D_DIM + 3] + a[D_DIM + 4];
        float acc = qd + 0.5f * tail;
        float h = floorf(acc * 0.25f);           // *0.25 == /4.0 exactly
        long long hi = (long long)h;
        int b = (int)(hi % 64); if (b < 0) b += 64;
        g_qbucket = b;
        g_scale = 0.83f / sqrtf(__int_as_float(g_maxbits));
    }
}

// -------- mask + deterministic sorted compaction (single block) --------
__global__ __launch_bounds__(1024) void k_scan(const float* __restrict__ a) {
    __shared__ int cnts[1024];
    int t = threadIdx.x;
    float s  = g_scale;
    float s2 = s * s;
    float a0 = a[D_DIM], a1 = a[D_DIM + 1], a2 = a[D_DIM + 2],
          a3 = a[D_DIM + 3], a4 = a[D_DIM + 4];
    int qb = g_qbucket;

    unsigned mask = 0u;
#pragma unroll 4
    for (int r = 0; r < 32; r++) {
        int i = (t << 5) | r;
        float n2  = s2 * g_sumsq[i];
        float acc = s * g_wa[i];
        float p = n2;              acc += p * a0;   // n2^1
        p *= p;                    acc += p * a1;   // n2^2
        p *= p;                    acc += p * a2;   // n2^4
        p *= p;                    acc += p * a3;   // n2^8
        p *= p;                    acc += p * a4;   // n2^16
        float h = floorf(acc * 0.25f);
        int b = (int)((long long)h % 64); if (b < 0) b += 64;
        if (b == qb) mask |= (1u << r);
    }
    int lc = __popc(mask);
    cnts[t] = lc;
    __syncthreads();
    // inclusive Hillis–Steele scan
    for (int off = 1; off < 1024; off <<= 1) {
        int v = (t >= off) ? cnts[t - off] : 0;
        __syncthreads();
        cnts[t] += v;
        __syncthreads();
    }
    int off = cnts[t] - lc;       // exclusive prefix
    for (int r = 0; r < 32; r++) {
        if ((mask >> r) & 1u) g_active[off++] = (t << 5) | r;
    }
    if (t == 1023) g_count = cnts[1023];
}

// -------- zero fill output --------
__global__ __launch_bounds__(256) void k_zero(float4* __restrict__ out, int n4) {
    int i = blockIdx.x * 256 + threadIdx.x;
    if (i < n4) out[i] = make_float4(0.f, 0.f, 0.f, 0.f);
}

// -------- compacted SGEMM: out[b, act[j]] = sum_d x[b,d] * W[act[j],d] --------
#define BM 64
#define BN 64
#define BK 16
__global__ __launch_bounds__(256) void k_gemm(const float* __restrict__ x,
                                              const float* __restrict__ W,
                                              float* __restrict__ out) {
    int cnt = g_count;
    int nt = blockIdx.y;                 // column tile (compacted index space)
    if (nt * BN >= cnt) return;
    int mt = blockIdx.x;                 // row tile (x fastest -> W tile L2 reuse)

    __shared__ float As[BK][BM];
    __shared__ float Bs[BK][BN];
    __shared__ int   acts[BN];

    int tid = threadIdx.x;
    if (tid < BN) {
        int j = nt * BN + tid;
        acts[tid] = (j < cnt) ? g_active[j] : g_active[nt * BN];  // safe dup
    }
    __syncthreads();

    int lr = tid >> 2;                   // 0..63 : row within tile
    int lk = (tid & 3) << 2;             // 0,4,8,12 : k offset (float4)
    const float* xp = x + (size_t)(mt * BM + lr) * D_DIM + lk;
    const float* wp = W + (size_t)acts[lr] * D_DIM + lk;

    int ty = tid >> 4;                   // 0..15
    int tx = tid & 15;                   // 0..15

    float acc[4][4] = {};

    for (int k0 = 0; k0 < D_DIM; k0 += BK) {
        float4 av = *reinterpret_cast<const float4*>(xp + k0);
        float4 bv = *reinterpret_cast<const float4*>(wp + k0);
        As[lk + 0][lr] = av.x; As[lk + 1][lr] = av.y;
        As[lk + 2][lr] = av.z; As[lk + 3][lr] = av.w;
        Bs[lk + 0][lr] = bv.x; Bs[lk + 1][lr] = bv.y;
        Bs[lk + 2][lr] = bv.z; Bs[lk + 3][lr] = bv.w;
        __syncthreads();
#pragma unroll
        for (int kk = 0; kk < BK; kk++) {
            float4 af = *reinterpret_cast<const float4*>(&As[kk][ty << 2]);
            float4 bf = *reinterpret_cast<const float4*>(&Bs[kk][tx << 2]);
            float am[4] = {af.x, af.y, af.z, af.w};
            float bm[4] = {bf.x, bf.y, bf.z, bf.w};
#pragma unroll
            for (int i = 0; i < 4; i++)
#pragma unroll
                for (int j = 0; j < 4; j++)
                    acc[i][j] = fmaf(am[i], bm[j], acc[i][j]);
        }
        __syncthreads();
    }

    int base_j = nt * BN + (tx << 2);
#pragma unroll
    for (int jj = 0; jj < 4; jj++) {
        int jg = base_j + jj;
        if (jg < cnt) {
            int ncol = acts[(tx << 2) + jj];
#pragma unroll
            for (int ii = 0; ii < 4; ii++) {
                out[(size_t)(mt * BM + (ty << 2) + ii) * N_ROWS + ncol] = acc[ii][jj];
            }
        }
    }
}

// -------- launch --------
extern "C" void kernel_launch(void* const* d_in, const int* in_sizes, int n_in,
                              void* d_out, int out_size) {
    const float* x = (const float*)d_in[0];   // [2048, 2048]
    const float* W = (const float*)d_in[1];   // [32768, 2048]
    const float* a = (const float*)d_in[2];   // [2053]
    float* out = (float*)d_out;               // [2048, 32768]

    k_init<<<1, 1>>>();
    k_rowstats<<<N_ROWS, 256>>>(W, a);
    k_colsum<<<D_DIM / 256, 256>>>(x);
    k_qhash<<<1, 256>>>(a);
    k_scan<<<1, 1024>>>(a);

    int n4 = out_size / 4;
    k_zero<<<(n4 + 255) / 256, 256>>>((float4*)out, n4);

    dim3 grid(B_DIM / BM, N_ROWS / BN);       // worst-case column tiles; early exit
    k_gemm<<<grid, 256>>>(x, W, out);
}

// round 3
// speedup vs baseline: 2.8856x; 2.8856x over previous
#include <cuda_runtime.h>
#include <cuda_bf16.h>
#include <cstdint>

#define N_ROWS 32768
#define D_DIM  2048
#define B_DIM  2048

// ---------------- device scratch ----------------
__device__ float g_sumsq[N_ROWS];
__device__ float g_wa[N_ROWS];
__device__ float g_colsum[D_DIM];
__device__ int   g_active[N_ROWS];
__device__ int   g_count;
__device__ int   g_maxbits;
__device__ int   g_qbucket;
__device__ float g_scale;
__device__ __nv_bfloat16 g_Whi[(size_t)N_ROWS * D_DIM];   // 128 MB
__device__ __nv_bfloat16 g_Wlo[(size_t)N_ROWS * D_DIM];   // 128 MB
__device__ __nv_bfloat16 g_xhi[(size_t)B_DIM * D_DIM];    // 8 MB
__device__ __nv_bfloat16 g_xlo[(size_t)B_DIM * D_DIM];    // 8 MB

// ---------------- PTX helpers (baseline ISA only) ----------------
__device__ __forceinline__ uint32_t smem_u32(const void* p) {
    uint32_t a;
    asm("{ .reg .u64 t; cvta.to.shared.u64 t, %1; cvt.u32.u64 %0, t; }" : "=r"(a) : "l"(p));
    return a;
}
__device__ __forceinline__ void cpa16(uint32_t saddr, const void* g) {
    asm volatile("cp.async.cg.shared.global [%0], [%1], 16;" :: "r"(saddr), "l"(g));
}
#define CP_COMMIT() asm volatile("cp.async.commit_group;" ::: "memory")
#define CP_WAIT2()  asm volatile("cp.async.wait_group 2;" ::: "memory")

__device__ __forceinline__ void ldsm_x4(uint32_t* r, uint32_t addr) {
    asm volatile("ldmatrix.sync.aligned.m8n8.x4.shared.b16 {%0,%1,%2,%3}, [%4];"
        : "=r"(r[0]), "=r"(r[1]), "=r"(r[2]), "=r"(r[3]) : "r"(addr));
}
__device__ __forceinline__ void ldsm_x2(uint32_t* r, uint32_t addr) {
    asm volatile("ldmatrix.sync.aligned.m8n8.x2.shared.b16 {%0,%1}, [%2];"
        : "=r"(r[0]), "=r"(r[1]) : "r"(addr));
}
__device__ __forceinline__ void mma_bf16(float* c, const uint32_t* a, const uint32_t* b) {
    asm volatile("mma.sync.aligned.m16n8k16.row.col.f32.bf16.bf16.f32 "
        "{%0,%1,%2,%3}, {%4,%5,%6,%7}, {%8,%9}, {%0,%1,%2,%3};"
        : "+f"(c[0]), "+f"(c[1]), "+f"(c[2]), "+f"(c[3])
        : "r"(a[0]), "r"(a[1]), "r"(a[2]), "r"(a[3]), "r"(b[0]), "r"(b[1]));
}

// ---------------- init ----------------
__global__ void k_init() { g_count = 0; g_maxbits = 0; }

// -------- per-row stats + W -> bf16 hi/lo split --------
__global__ __launch_bounds__(256) void k_rowstats(const float* __restrict__ W,
                                                  const float* __restrict__ a) {
    int row = blockIdx.x;
    int tid = threadIdx.x;
    const float4* wr = reinterpret_cast<const float4*>(W + (size_t)row * D_DIM);
    const float4* a4 = reinterpret_cast<const float4*>(a);
    __nv_bfloat162* whi = reinterpret_cast<__nv_bfloat162*>(g_Whi + (size_t)row * D_DIM);
    __nv_bfloat162* wlo = reinterpret_cast<__nv_bfloat162*>(g_Wlo + (size_t)row * D_DIM);

    float ss = 0.f, wa = 0.f;
#pragma unroll
    for (int i = 0; i < 2; i++) {
        int idx = tid + i * 256;            // 512 float4 per row
        float4 w  = wr[idx];
        float4 av = __ldg(&a4[idx]);
        ss += w.x * w.x + w.y * w.y + w.z * w.z + w.w * w.w;
        wa += w.x * av.x + w.y * av.y + w.z * av.z + w.w * av.w;
        __nv_bfloat16 hx = __float2bfloat16_rn(w.x), hy = __float2bfloat16_rn(w.y);
        __nv_bfloat16 hz = __float2bfloat16_rn(w.z), hw = __float2bfloat16_rn(w.w);
        __nv_bfloat16 lx = __float2bfloat16_rn(w.x - __bfloat162float(hx));
        __nv_bfloat16 ly = __float2bfloat16_rn(w.y - __bfloat162float(hy));
        __nv_bfloat16 lz = __float2bfloat16_rn(w.z - __bfloat162float(hz));
        __nv_bfloat16 lw = __float2bfloat16_rn(w.w - __bfloat162float(hw));
        whi[idx * 2 + 0] = __halves2bfloat162(hx, hy);
        whi[idx * 2 + 1] = __halves2bfloat162(hz, hw);
        wlo[idx * 2 + 0] = __halves2bfloat162(lx, ly);
        wlo[idx * 2 + 1] = __halves2bfloat162(lz, lw);
    }
    for (int o = 16; o; o >>= 1) {
        ss += __shfl_down_sync(0xFFFFFFFFu, ss, o);
        wa += __shfl_down_sync(0xFFFFFFFFu, wa, o);
    }
    __shared__ float sss[8], swa[8];
    int wid = tid >> 5, lane = tid & 31;
    if (lane == 0) { sss[wid] = ss; swa[wid] = wa; }
    __syncthreads();
    if (tid == 0) {
        double S = 0.0, A = 0.0;
#pragma unroll
        for (int i = 0; i < 8; i++) { S += sss[i]; A += swa[i]; }
        float Sf = (float)S;
        g_sumsq[row] = Sf;
        g_wa[row]    = (float)A;
        atomicMax(&g_maxbits, __float_as_int(Sf));
    }
}

// -------- x -> bf16 hi/lo --------
__global__ __launch_bounds__(256) void k_convx(const float* __restrict__ x) {
    int i = blockIdx.x * 256 + threadIdx.x;
    float4 v = reinterpret_cast<const float4*>(x)[i];
    __nv_bfloat16 hx = __float2bfloat16_rn(v.x), hy = __float2bfloat16_rn(v.y);
    __nv_bfloat16 hz = __float2bfloat16_rn(v.z), hw = __float2bfloat16_rn(v.w);
    __nv_bfloat16 lx = __float2bfloat16_rn(v.x - __bfloat162float(hx));
    __nv_bfloat16 ly = __float2bfloat16_rn(v.y - __bfloat162float(hy));
    __nv_bfloat16 lz = __float2bfloat16_rn(v.z - __bfloat162float(hz));
    __nv_bfloat16 lw = __float2bfloat16_rn(v.w - __bfloat162float(hw));
    __nv_bfloat162* xh = reinterpret_cast<__nv_bfloat162*>(g_xhi);
    __nv_bfloat162* xl = reinterpret_cast<__nv_bfloat162*>(g_xlo);
    xh[i * 2 + 0] = __halves2bfloat162(hx, hy);
    xh[i * 2 + 1] = __halves2bfloat162(hz, hw);
    xl[i * 2 + 0] = __halves2bfloat162(lx, ly);
    xl[i * 2 + 1] = __halves2bfloat162(lz, lw);
}

// -------- column sums of x --------
__global__ __launch_bounds__(256) void k_colsum(const float* __restrict__ x) {
    int d = blockIdx.x * 256 + threadIdx.x;
    float a0 = 0.f, a1 = 0.f, a2 = 0.f, a3 = 0.f;
    for (int b = 0; b < B_DIM; b += 4) {
        a0 += x[(size_t)(b + 0) * D_DIM + d];
        a1 += x[(size_t)(b + 1) * D_DIM + d];
        a2 += x[(size_t)(b + 2) * D_DIM + d];
        a3 += x[(size_t)(b + 3) * D_DIM + d];
    }
    g_colsum[d] = (float)(((double)a0 + a1) + ((double)a2 + a3));
}

// -------- q bucket + scale --------
__global__ __launch_bounds__(256) void k_qhash(const float* __restrict__ a) {
    __shared__ double s_n2[256], s_ca[256];
    int t = threadIdx.x;
    double n2 = 0.0, ca = 0.0;
    for (int d = t; d < D_DIM; d += 256) {
        float c = g_colsum[d];
        n2 += (double)c * (double)c;
        ca += (double)c * (double)a[d];
    }
    s_n2[t] = n2; s_ca[t] = ca;
    __syncthreads();
    for (int off = 128; off; off >>= 1) {
        if (t < off) { s_n2[t] += s_n2[t + off]; s_ca[t] += s_ca[t + off]; }
        __syncthreads();
    }
    if (t == 0) {
        float nrm = sqrtf((float)s_n2[0]);
        float qd  = (float)s_ca[0] / nrm;
        float tail = a[D_DIM] + a[D_DIM + 1] + a[D_DIM + 2] + a[D_DIM + 3] + a[D_DIM + 4];
        float acc = qd + 0.5f * tail;
        float h = floorf(acc * 0.25f);
        long long hi = (long long)h;
        int b = (int)(hi % 64); if (b < 0) b += 64;
        g_qbucket = b;
        g_scale = 0.83f / sqrtf(__int_as_float(g_maxbits));
    }
}

// -------- mask + deterministic sorted compaction --------
__global__ __launch_bounds__(1024) void k_scan(const float* __restrict__ a) {
    __shared__ int cnts[1024];
    int t = threadIdx.x;
    float s  = g_scale;
    float s2 = s * s;
    float a0 = a[D_DIM], a1 = a[D_DIM + 1], a2 = a[D_DIM + 2],
          a3 = a[D_DIM + 3], a4 = a[D_DIM + 4];
    int qb = g_qbucket;

    unsigned mask = 0u;
#pragma unroll 4
    for (int r = 0; r < 32; r++) {
        int i = (t << 5) | r;
        float n2  = s2 * g_sumsq[i];
        float acc = s * g_wa[i];
        float p = n2;              acc += p * a0;
        p *= p;                    acc += p * a1;
        p *= p;                    acc += p * a2;
        p *= p;                    acc += p * a3;
        p *= p;                    acc += p * a4;
        float h = floorf(acc * 0.25f);
        int b = (int)((long long)h % 64); if (b < 0) b += 64;
        if (b == qb) mask |= (1u << r);
    }
    int lc = __popc(mask);
    cnts[t] = lc;
    __syncthreads();
    for (int off = 1; off < 1024; off <<= 1) {
        int v = (t >= off) ? cnts[t - off] : 0;
        __syncthreads();
        cnts[t] += v;
        __syncthreads();
    }
    int off = cnts[t] - lc;
    for (int r = 0; r < 32; r++) {
        if ((mask >> r) & 1u) g_active[off++] = (t << 5) | r;
    }
    if (t == 1023) g_count = cnts[1023];
}

// -------- zero fill output --------
__global__ __launch_bounds__(256) void k_zero(float4* __restrict__ out, int n4) {
    int i = blockIdx.x * 256 + threadIdx.x;
    if (i < n4) out[i] = make_float4(0.f, 0.f, 0.f, 0.f);
}

// ================= mma.sync compacted GEMM =================
// BM=128 (x rows), BN=128 (active cols), BK=32, 8 warps (2x4), warp tile 64x32
#define BM 128
#define BN 128
#define BK 32
#define NCHUNK (D_DIM / BK)
#define NSTAGE 3
#define ROWB   80                       // padded row bytes (40 bf16)
#define TILE_B (128 * ROWB)             // 10240 B per split-tile
#define STAGE_B (4 * TILE_B)            // Ahi,Alo,Bhi,Blo
#define GEMM_SMEM (1024 + NSTAGE * STAGE_B)

__device__ __forceinline__ void load_stage(uint32_t sbase, const int* acts_s,
                                           int mrow0, int k0, int tid) {
#pragma unroll
    for (int i = 0; i < 2; i++) {
        int idx = tid + i * 256;                   // 512: A rows x 4 chunks
        int r = idx >> 2, ch = idx & 3;
        size_t g = (size_t)(mrow0 + r) * D_DIM + k0 + ch * 8;
        uint32_t dst = sbase + r * ROWB + ch * 16;
        cpa16(dst, g_xhi + g);
        cpa16(dst + TILE_B, g_xlo + g);
    }
#pragma unroll
    for (int i = 0; i < 2; i++) {
        int idx = tid + i * 256;
        int r = idx >> 2, ch = idx & 3;
        size_t g = (size_t)acts_s[r] * D_DIM + k0 + ch * 8;
        uint32_t dst = sbase + 2 * TILE_B + r * ROWB + ch * 16;
        cpa16(dst, g_Whi + g);
        cpa16(dst + TILE_B, g_Wlo + g);
    }
}

__global__ void __launch_bounds__(256, 1) k_gemm(float* __restrict__ out) {
    extern __shared__ char smem[];
    int cnt = g_count;
    int nt = blockIdx.y;
    if (nt * BN >= cnt) return;
    int mt = blockIdx.x;
    int tid = threadIdx.x;
    int lane = tid & 31, w = tid >> 5;
    int wm = w & 1, wn = w >> 1;                   // 2 x 4 warps
    uint32_t sb = smem_u32(smem);
    int* acts_s = (int*)smem;
    if (tid < BN) {
        int j = nt * BN + tid;
        acts_s[tid] = g_active[j < cnt ? j : cnt - 1];
    }
    __syncthreads();
    int mrow0 = mt * BM;

    for (int s = 0; s < NSTAGE; s++) {
        load_stage(sb + 1024 + s * STAGE_B, acts_s, mrow0, s * BK, tid);
        CP_COMMIT();
    }

    float acc[4][4][4] = {};
    // precomputed ldmatrix base offsets
    uint32_t a_ro = (uint32_t)(wm * 64 + (lane & 15)) * ROWB + (uint32_t)(lane >> 4) * 16;
    uint32_t b_ro = (uint32_t)(wn * 32 + (lane & 7)) * ROWB + (uint32_t)((lane >> 3) & 1) * 16;

    int sidx = 0;
    for (int c = 0; c < NCHUNK; c++) {
        CP_WAIT2();
        __syncthreads();
        uint32_t st = sb + 1024 + sidx * STAGE_B;
#pragma unroll
        for (int ks = 0; ks < 2; ks++) {
            uint32_t ah[4][4], al[4][4], bh[4][2], bl[4][2];
            uint32_t ab = st + a_ro + ks * 32;
            uint32_t bb = st + 2 * TILE_B + b_ro + ks * 32;
#pragma unroll
            for (int mi = 0; mi < 4; mi++) {
                uint32_t addr = ab + mi * (16 * ROWB);
                ldsm_x4(ah[mi], addr);
                ldsm_x4(al[mi], addr + TILE_B);
            }
#pragma unroll
            for (int ni = 0; ni < 4; ni++) {
                uint32_t addr = bb + ni * (8 * ROWB);
                ldsm_x2(bh[ni], addr);
                ldsm_x2(bl[ni], addr + TILE_B);
            }
#pragma unroll
            for (int mi = 0; mi < 4; mi++)
#pragma unroll
                for (int ni = 0; ni < 4; ni++)
                    mma_bf16(acc[mi][ni], ah[mi], bh[ni]);
#pragma unroll
            for (int mi = 0; mi < 4; mi++)
#pragma unroll
                for (int ni = 0; ni < 4; ni++) {
                    mma_bf16(acc[mi][ni], ah[mi], bl[ni]);
                    mma_bf16(acc[mi][ni], al[mi], bh[ni]);
                }
        }
        __syncthreads();
        int nc = c + NSTAGE;
        if (nc < NCHUNK)
            load_stage(sb + 1024 + sidx * STAGE_B, acts_s, mrow0, nc * BK, tid);
        CP_COMMIT();
        sidx = (sidx + 1 == NSTAGE) ? 0 : sidx + 1;
    }

    // epilogue: scatter to out[row][acts[j]]
    int lim = cnt - nt * BN; if (lim > BN) lim = BN;
#pragma unroll
    for (int mi = 0; mi < 4; mi++) {
        int r0 = mrow0 + wm * 64 + mi * 16 + (lane >> 2);
        float* o0 = out + (size_t)r0 * N_ROWS;
        float* o1 = o0 + (size_t)8 * N_ROWS;
#pragma unroll
        for (int ni = 0; ni < 4; ni++) {
            int jl = wn * 32 + ni * 8 + (lane & 3) * 2;
            if (jl < lim) {
                int cx = acts_s[jl];
                o0[cx] = acc[mi][ni][0];
                o1[cx] = acc[mi][ni][2];
            }
            if (jl + 1 < lim) {
                int cx = acts_s[jl + 1];
                o0[cx] = acc[mi][ni][1];
                o1[cx] = acc[mi][ni][3];
            }
        }
    }
}

// ---------------- launch ----------------
extern "C" void kernel_launch(void* const* d_in, const int* in_sizes, int n_in,
                              void* d_out, int out_size) {
    const float* x = (const float*)d_in[0];   // [2048, 2048]
    const float* W = (const float*)d_in[1];   // [32768, 2048]
    const float* a = (const float*)d_in[2];   // [2053]
    float* out = (float*)d_out;               // [2048, 32768]

    cudaFuncSetAttribute(k_gemm, cudaFuncAttributeMaxDynamicSharedMemorySize, GEMM_SMEM);

    k_init<<<1, 1>>>();
    k_rowstats<<<N_ROWS, 256>>>(W, a);
    k_convx<<<(B_DIM * D_DIM / 4) / 256, 256>>>(x);
    k_colsum<<<D_DIM / 256, 256>>>(x);
    k_qhash<<<1, 256>>>(a);
    k_scan<<<1, 1024>>>(a);

    int n4 = out_size / 4;
    k_zero<<<(n4 + 255) / 256, 256>>>((float4*)out, n4);

    dim3 grid(B_DIM / BM, N_ROWS / BN);   // mt fast -> W tile L2 reuse
    k_gemm<<<grid, 256, GEMM_SMEM>>>(out);
}

// round 4
// speedup vs baseline: 6.4140x; 2.2228x over previous
#include <cuda_runtime.h>
#include <cuda_fp16.h>
#include <cstdint>

#define N_ROWS 32768
#define D_DIM  2048
#define B_DIM  2048

// ---------------- device scratch ----------------
__device__ float g_sumsq[N_ROWS];
__device__ float g_wa[N_ROWS];
__device__ float g_part[16 * D_DIM];
__device__ float g_colsum[D_DIM];
__device__ int   g_active[N_ROWS];
__device__ int   g_count;
__device__ int   g_maxbits;
__device__ int   g_qbucket;
__device__ float g_scale;
__device__ __half g_Wh[(size_t)N_ROWS * D_DIM];   // 128 MB... no: 64 MB
__device__ __half g_xh[(size_t)B_DIM * D_DIM];    // 8 MB

// ---------------- PTX helpers (baseline ISA only) ----------------
__device__ __forceinline__ uint32_t smem_u32(const void* p) {
    uint32_t a;
    asm("{ .reg .u64 t; cvta.to.shared.u64 t, %1; cvt.u32.u64 %0, t; }" : "=r"(a) : "l"(p));
    return a;
}
__device__ __forceinline__ void cpa16(uint32_t saddr, const void* g) {
    asm volatile("cp.async.cg.shared.global [%0], [%1], 16;" :: "r"(saddr), "l"(g));
}
#define CP_COMMIT() asm volatile("cp.async.commit_group;" ::: "memory")
#define CP_WAIT3()  asm volatile("cp.async.wait_group 3;" ::: "memory")

__device__ __forceinline__ void ldsm_x4(uint32_t* r, uint32_t addr) {
    asm volatile("ldmatrix.sync.aligned.m8n8.x4.shared.b16 {%0,%1,%2,%3}, [%4];"
        : "=r"(r[0]), "=r"(r[1]), "=r"(r[2]), "=r"(r[3]) : "r"(addr));
}
__device__ __forceinline__ void ldsm_x2(uint32_t* r, uint32_t addr) {
    asm volatile("ldmatrix.sync.aligned.m8n8.x2.shared.b16 {%0,%1}, [%2];"
        : "=r"(r[0]), "=r"(r[1]) : "r"(addr));
}
__device__ __forceinline__ void mma_f16(float* c, const uint32_t* a, const uint32_t* b) {
    asm volatile("mma.sync.aligned.m16n8k16.row.col.f32.f16.f16.f32 "
        "{%0,%1,%2,%3}, {%4,%5,%6,%7}, {%8,%9}, {%0,%1,%2,%3};"
        : "+f"(c[0]), "+f"(c[1]), "+f"(c[2]), "+f"(c[3])
        : "r"(a[0]), "r"(a[1]), "r"(a[2]), "r"(a[3]), "r"(b[0]), "r"(b[1]));
}

// ---------------- init ----------------
__global__ void k_init() { g_count = 0; g_maxbits = 0; }

// -------- per-row stats + W -> f16 --------
__global__ __launch_bounds__(256) void k_rowstats(const float* __restrict__ W,
                                                  const float* __restrict__ a) {
    int row = blockIdx.x;
    int tid = threadIdx.x;
    const float4* wr = reinterpret_cast<const float4*>(W + (size_t)row * D_DIM);
    const float4* a4 = reinterpret_cast<const float4*>(a);
    __half2* wh = reinterpret_cast<__half2*>(g_Wh + (size_t)row * D_DIM);

    float ss = 0.f, wa = 0.f;
#pragma unroll
    for (int i = 0; i < 2; i++) {
        int idx = tid + i * 256;            // 512 float4 per row
        float4 w  = wr[idx];
        float4 av = __ldg(&a4[idx]);
        ss += w.x * w.x + w.y * w.y + w.z * w.z + w.w * w.w;
        wa += w.x * av.x + w.y * av.y + w.z * av.z + w.w * av.w;
        wh[idx * 2 + 0] = __floats2half2_rn(w.x, w.y);
        wh[idx * 2 + 1] = __floats2half2_rn(w.z, w.w);
    }
    for (int o = 16; o; o >>= 1) {
        ss += __shfl_down_sync(0xFFFFFFFFu, ss, o);
        wa += __shfl_down_sync(0xFFFFFFFFu, wa, o);
    }
    __shared__ float sss[8], swa[8];
    int wid = tid >> 5, lane = tid & 31;
    if (lane == 0) { sss[wid] = ss; swa[wid] = wa; }
    __syncthreads();
    if (tid == 0) {
        double S = 0.0, A = 0.0;
#pragma unroll
        for (int i = 0; i < 8; i++) { S += sss[i]; A += swa[i]; }
        float Sf = (float)S;
        g_sumsq[row] = Sf;
        g_wa[row]    = (float)A;
        atomicMax(&g_maxbits, __float_as_int(Sf));
    }
}

// -------- x -> f16 --------
__global__ __launch_bounds__(256) void k_convx(const float* __restrict__ x) {
    int i = blockIdx.x * 256 + threadIdx.x;
    float4 v = reinterpret_cast<const float4*>(x)[i];
    __half2* xh = reinterpret_cast<__half2*>(g_xh);
    xh[i * 2 + 0] = __floats2half2_rn(v.x, v.y);
    xh[i * 2 + 1] = __floats2half2_rn(v.z, v.w);
}

// -------- column sums of x: stage 1 (deterministic partials) --------
__global__ __launch_bounds__(256) void k_colsum1(const float* __restrict__ x) {
    int d = blockIdx.x * 256 + threadIdx.x;
    int p = blockIdx.y;                       // 16 row-partitions of 128 rows
    const float* xp = x + (size_t)p * 128 * D_DIM + d;
    float s0 = 0.f, s1 = 0.f;
    for (int b = 0; b < 128; b += 2) {
        s0 += xp[(size_t)b * D_DIM];
        s1 += xp[(size_t)(b + 1) * D_DIM];
    }
    g_part[p * D_DIM + d] = s0 + s1;
}
// -------- stage 2: fixed-order combine --------
__global__ __launch_bounds__(256) void k_colsum2() {
    int d = blockIdx.x * 256 + threadIdx.x;
    double s = 0.0;
#pragma unroll
    for (int p = 0; p < 16; p++) s += (double)g_part[p * D_DIM + d];
    g_colsum[d] = (float)s;
}

// -------- q bucket + scale --------
__global__ __launch_bounds__(256) void k_qhash(const float* __restrict__ a) {
    __shared__ double s_n2[256], s_ca[256];
    int t = threadIdx.x;
    double n2 = 0.0, ca = 0.0;
    for (int d = t; d < D_DIM; d += 256) {
        float c = g_colsum[d];
        n2 += (double)c * (double)c;
        ca += (double)c * (double)a[d];
    }
    s_n2[t] = n2; s_ca[t] = ca;
    __syncthreads();
    for (int off = 128; off; off >>= 1) {
        if (t < off) { s_n2[t] += s_n2[t + off]; s_ca[t] += s_ca[t + off]; }
        __syncthreads();
    }
    if (t == 0) {
        float nrm = sqrtf((float)s_n2[0]);
        float qd  = (float)s_ca[0] / nrm;
        float tail = a[D_DIM] + a[D_DIM + 1] + a[D_DIM + 2] + a[D_DIM + 3] + a[D_DIM + 4];
        float acc = qd + 0.5f * tail;
        float h = floorf(acc * 0.25f);
        long long hi = (long long)h;
        int b = (int)(hi % 64); if (b < 0) b += 64;
        g_qbucket = b;
        g_scale = 0.83f / sqrtf(__int_as_float(g_maxbits));
    }
}

// -------- mask + deterministic sorted compaction --------
__global__ __launch_bounds__(1024) void k_scan(const float* __restrict__ a) {
    __shared__ int cnts[1024];
    int t = threadIdx.x;
    float s  = g_scale;
    float s2 = s * s;
    float a0 = a[D_DIM], a1 = a[D_DIM + 1], a2 = a[D_DIM + 2],
          a3 = a[D_DIM + 3], a4 = a[D_DIM + 4];
    int qb = g_qbucket;

    unsigned mask = 0u;
#pragma unroll 4
    for (int r = 0; r < 32; r++) {
        int i = (t << 5) | r;
        float n2  = s2 * g_sumsq[i];
        float acc = s * g_wa[i];
        float p = n2;              acc += p * a0;
        p *= p;                    acc += p * a1;
        p *= p;                    acc += p * a2;
        p *= p;                    acc += p * a3;
        p *= p;                    acc += p * a4;
        float h = floorf(acc * 0.25f);
        int b = (int)((long long)h % 64); if (b < 0) b += 64;
        if (b == qb) mask |= (1u << r);
    }
    int lc = __popc(mask);
    cnts[t] = lc;
    __syncthreads();
    for (int off = 1; off < 1024; off <<= 1) {
        int v = (t >= off) ? cnts[t - off] : 0;
        __syncthreads();
        cnts[t] += v;
        __syncthreads();
    }
    int off = cnts[t] - lc;
    for (int r = 0; r < 32; r++) {
        if ((mask >> r) & 1u) g_active[off++] = (t << 5) | r;
    }
    if (t == 1023) g_count = cnts[1023];
}

// ================= single-pass f16 mma.sync compacted GEMM =================
// BM=128, BN=128, BK=64, 8 warps (2x4), warp tile 64x32
#define BM 128
#define BN 128
#define BK 64
#define NCHUNK (D_DIM / BK)
#define NSTAGE 4
#define ROWB   144                      // 64 f16 = 128B data + 16B pad
#define TILE_B (128 * ROWB)             // 18432 B
#define STAGE_B (2 * TILE_B)            // XH, WH
#define GEMM_SMEM (1024 + NSTAGE * STAGE_B)

__device__ __forceinline__ void load_stage(uint32_t sbase, const int* acts_s,
                                           int mrow0, int k0, int tid) {
#pragma unroll
    for (int i = 0; i < 4; i++) {
        int idx = tid + i * 256;                 // 1024 cpa16 for X tile
        int r = idx >> 3, ch = idx & 7;
        size_t g = (size_t)(mrow0 + r) * D_DIM + k0 + ch * 8;
        cpa16(sbase + r * ROWB + ch * 16, g_xh + g);
    }
#pragma unroll
    for (int i = 0; i < 4; i++) {
        int idx = tid + i * 256;                 // 1024 cpa16 for W tile
        int r = idx >> 3, ch = idx & 7;
        size_t g = (size_t)acts_s[r] * D_DIM + k0 + ch * 8;
        cpa16(sbase + TILE_B + r * ROWB + ch * 16, g_Wh + g);
    }
}

__global__ void __launch_bounds__(256, 1) k_gemm(float* __restrict__ out) {
    extern __shared__ char smem[];
    int cnt = g_count;
    int nt = blockIdx.y;
    if (nt * BN >= cnt) return;
    int mt = blockIdx.x;
    int tid = threadIdx.x;
    int lane = tid & 31, w = tid >> 5;
    int wm = w & 1, wn = w >> 1;                 // 2 x 4 warps
    uint32_t sb = smem_u32(smem);
    int* acts_s = (int*)smem;
    if (tid < BN) {
        int j = nt * BN + tid;
        acts_s[tid] = g_active[j < cnt ? j : cnt - 1];
    }
    __syncthreads();
    int mrow0 = mt * BM;

    for (int s = 0; s < NSTAGE; s++) {
        load_stage(sb + 1024 + s * STAGE_B, acts_s, mrow0, s * BK, tid);
        CP_COMMIT();
    }

    float acc[4][4][4] = {};
    uint32_t a_ro = (uint32_t)(wm * 64 + (lane & 15)) * ROWB + (uint32_t)(lane >> 4) * 16;
    uint32_t b_ro = (uint32_t)(wn * 32 + (lane & 7)) * ROWB + (uint32_t)((lane >> 3) & 1) * 16;

    int sidx = 0;
    for (int c = 0; c < NCHUNK; c++) {
        CP_WAIT3();
        __syncthreads();
        uint32_t st = sb + 1024 + sidx * STAGE_B;
#pragma unroll
        for (int ks = 0; ks < 4; ks++) {
            uint32_t ah[4][4], bh[4][2];
            uint32_t ab = st + a_ro + ks * 32;
            uint32_t bb = st + TILE_B + b_ro + ks * 32;
#pragma unroll
            for (int mi = 0; mi < 4; mi++)
                ldsm_x4(ah[mi], ab + mi * (16 * ROWB));
#pragma unroll
            for (int ni = 0; ni < 4; ni++)
                ldsm_x2(bh[ni], bb + ni * (8 * ROWB));
#pragma unroll
            for (int mi = 0; mi < 4; mi++)
#pragma unroll
                for (int ni = 0; ni < 4; ni++)
                    mma_f16(acc[mi][ni], ah[mi], bh[ni]);
        }
        __syncthreads();
        int nc = c + NSTAGE;
        if (nc < NCHUNK)
            load_stage(sb + 1024 + sidx * STAGE_B, acts_s, mrow0, nc * BK, tid);
        CP_COMMIT();
        sidx = (sidx + 1 == NSTAGE) ? 0 : sidx + 1;
    }

    // epilogue: scatter to out[row][acts[j]]
    int lim = cnt - nt * BN; if (lim > BN) lim = BN;
#pragma unroll
    for (int mi = 0; mi < 4; mi++) {
        int r0 = mrow0 + wm * 64 + mi * 16 + (lane >> 2);
        float* o0 = out + (size_t)r0 * N_ROWS;
        float* o1 = o0 + (size_t)8 * N_ROWS;
#pragma unroll
        for (int ni = 0; ni < 4; ni++) {
            int jl = wn * 32 + ni * 8 + (lane & 3) * 2;
            if (jl < lim) {
                int cx = acts_s[jl];
                o0[cx] = acc[mi][ni][0];
                o1[cx] = acc[mi][ni][2];
            }
            if (jl + 1 < lim) {
                int cx = acts_s[jl + 1];
                o0[cx] = acc[mi][ni][1];
                o1[cx] = acc[mi][ni][3];
            }
        }
    }
}

// ---------------- launch ----------------
extern "C" void kernel_launch(void* const* d_in, const int* in_sizes, int n_in,
                              void* d_out, int out_size) {
    const float* x = (const float*)d_in[0];   // [2048, 2048]
    const float* W = (const float*)d_in[1];   // [32768, 2048]
    const float* a = (const float*)d_in[2];   // [2053]
    float* out = (float*)d_out;               // [2048, 32768]

    cudaFuncSetAttribute(k_gemm, cudaFuncAttributeMaxDynamicSharedMemorySize, GEMM_SMEM);

    k_init<<<1, 1>>>();
    k_rowstats<<<N_ROWS, 256>>>(W, a);
    k_convx<<<(B_DIM * D_DIM / 4) / 256, 256>>>(x);
    dim3 csg(D_DIM / 256, 16);
    k_colsum1<<<csg, 256>>>(x);
    k_colsum2<<<D_DIM / 256, 256>>>();
    k_qhash<<<1, 256>>>(a);
    k_scan<<<1, 1024>>>(a);

    cudaMemsetAsync(d_out, 0, (size_t)out_size * sizeof(float));

    dim3 grid(B_DIM / BM, N_ROWS / BN);   // mt fast -> W tile L2 reuse
    k_gemm<<<grid, 256, GEMM_SMEM>>>(out);
}

// round 5
// speedup vs baseline: 6.8043x; 1.0608x over previous
#include <cuda_runtime.h>
#include <cuda_fp16.h>
#include <cstdint>

#define N_ROWS 32768
#define D_DIM  2048
#define B_DIM  2048

// ---------------- device scratch ----------------
__device__ float g_sumsq[N_ROWS];
__device__ float g_wa[N_ROWS];
__device__ float g_part[16 * D_DIM];
__device__ float g_colsum[D_DIM];
__device__ int   g_active[N_ROWS];
__device__ int   g_count;
__device__ int   g_maxbits;
__device__ int   g_qbucket;
__device__ float g_scale;
__device__ __half g_Wh[(size_t)N_ROWS * D_DIM];   // 64 MB
__device__ __half g_xh[(size_t)B_DIM * D_DIM];    // 8 MB

// ---------------- PTX helpers (baseline ISA only) ----------------
__device__ __forceinline__ uint32_t smem_u32(const void* p) {
    uint32_t a;
    asm("{ .reg .u64 t; cvta.to.shared.u64 t, %1; cvt.u32.u64 %0, t; }" : "=r"(a) : "l"(p));
    return a;
}
__device__ __forceinline__ void cpa16(uint32_t saddr, const void* g) {
    asm volatile("cp.async.cg.shared.global [%0], [%1], 16;" :: "r"(saddr), "l"(g));
}
#define CP_COMMIT() asm volatile("cp.async.commit_group;" ::: "memory")
#define CP_WAIT2()  asm volatile("cp.async.wait_group 2;" ::: "memory")

__device__ __forceinline__ void ldsm_x4(uint32_t* r, uint32_t addr) {
    asm volatile("ldmatrix.sync.aligned.m8n8.x4.shared.b16 {%0,%1,%2,%3}, [%4];"
        : "=r"(r[0]), "=r"(r[1]), "=r"(r[2]), "=r"(r[3]) : "r"(addr));
}
__device__ __forceinline__ void mma_f16(float* c, const uint32_t* a, const uint32_t* b) {
    asm volatile("mma.sync.aligned.m16n8k16.row.col.f32.f16.f16.f32 "
        "{%0,%1,%2,%3}, {%4,%5,%6,%7}, {%8,%9}, {%0,%1,%2,%3};"
        : "+f"(c[0]), "+f"(c[1]), "+f"(c[2]), "+f"(c[3])
        : "r"(a[0]), "r"(a[1]), "r"(a[2]), "r"(a[3]), "r"(b[0]), "r"(b[1]));
}

// ---------------- init ----------------
__global__ void k_init() { g_count = 0; g_maxbits = 0; }

// -------- per-row stats + W -> f16 --------
__global__ __launch_bounds__(256) void k_rowstats(const float* __restrict__ W,
                                                  const float* __restrict__ a) {
    int row = blockIdx.x;
    int tid = threadIdx.x;
    const float4* wr = reinterpret_cast<const float4*>(W + (size_t)row * D_DIM);
    const float4* a4 = reinterpret_cast<const float4*>(a);
    __half2* wh = reinterpret_cast<__half2*>(g_Wh + (size_t)row * D_DIM);

    float ss = 0.f, wa = 0.f;
#pragma unroll
    for (int i = 0; i < 2; i++) {
        int idx = tid + i * 256;            // 512 float4 per row
        float4 w  = wr[idx];
        float4 av = __ldg(&a4[idx]);
        ss += w.x * w.x + w.y * w.y + w.z * w.z + w.w * w.w;
        wa += w.x * av.x + w.y * av.y + w.z * av.z + w.w * av.w;
        wh[idx * 2 + 0] = __floats2half2_rn(w.x, w.y);
        wh[idx * 2 + 1] = __floats2half2_rn(w.z, w.w);
    }
    for (int o = 16; o; o >>= 1) {
        ss += __shfl_down_sync(0xFFFFFFFFu, ss, o);
        wa += __shfl_down_sync(0xFFFFFFFFu, wa, o);
    }
    __shared__ float sss[8], swa[8];
    int wid = tid >> 5, lane = tid & 31;
    if (lane == 0) { sss[wid] = ss; swa[wid] = wa; }
    __syncthreads();
    if (tid == 0) {
        double S = 0.0, A = 0.0;
#pragma unroll
        for (int i = 0; i < 8; i++) { S += sss[i]; A += swa[i]; }
        float Sf = (float)S;
        g_sumsq[row] = Sf;
        g_wa[row]    = (float)A;
        atomicMax(&g_maxbits, __float_as_int(Sf));
    }
}

// -------- x -> f16 --------
__global__ __launch_bounds__(256) void k_convx(const float* __restrict__ x) {
    int i = blockIdx.x * 256 + threadIdx.x;
    float4 v = reinterpret_cast<const float4*>(x)[i];
    __half2* xh = reinterpret_cast<__half2*>(g_xh);
    xh[i * 2 + 0] = __floats2half2_rn(v.x, v.y);
    xh[i * 2 + 1] = __floats2half2_rn(v.z, v.w);
}

// -------- column sums of x: stage 1 (deterministic partials) --------
__global__ __launch_bounds__(256) void k_colsum1(const float* __restrict__ x) {
    int d = blockIdx.x * 256 + threadIdx.x;
    int p = blockIdx.y;                       // 16 row-partitions of 128 rows
    const float* xp = x + (size_t)p * 128 * D_DIM + d;
    float s0 = 0.f, s1 = 0.f;
    for (int b = 0; b < 128; b += 2) {
        s0 += xp[(size_t)b * D_DIM];
        s1 += xp[(size_t)(b + 1) * D_DIM];
    }
    g_part[p * D_DIM + d] = s0 + s1;
}
// -------- stage 2: fixed-order combine --------
__global__ __launch_bounds__(256) void k_colsum2() {
    int d = blockIdx.x * 256 + threadIdx.x;
    double s = 0.0;
#pragma unroll
    for (int p = 0; p < 16; p++) s += (double)g_part[p * D_DIM + d];
    g_colsum[d] = (float)s;
}

// -------- q bucket + scale --------
__global__ __launch_bounds__(256) void k_qhash(const float* __restrict__ a) {
    __shared__ double s_n2[256], s_ca[256];
    int t = threadIdx.x;
    double n2 = 0.0, ca = 0.0;
    for (int d = t; d < D_DIM; d += 256) {
        float c = g_colsum[d];
        n2 += (double)c * (double)c;
        ca += (double)c * (double)a[d];
    }
    s_n2[t] = n2; s_ca[t] = ca;
    __syncthreads();
    for (int off = 128; off; off >>= 1) {
        if (t < off) { s_n2[t] += s_n2[t + off]; s_ca[t] += s_ca[t + off]; }
        __syncthreads();
    }
    if (t == 0) {
        float nrm = sqrtf((float)s_n2[0]);
        float qd  = (float)s_ca[0] / nrm;
        float tail = a[D_DIM] + a[D_DIM + 1] + a[D_DIM + 2] + a[D_DIM + 3] + a[D_DIM + 4];
        float acc = qd + 0.5f * tail;
        float h = floorf(acc * 0.25f);
        long long hi = (long long)h;
        int b = (int)(hi % 64); if (b < 0) b += 64;
        g_qbucket = b;
        g_scale = 0.83f / sqrtf(__int_as_float(g_maxbits));
    }
}

// -------- mask + deterministic sorted compaction --------
__global__ __launch_bounds__(1024) void k_scan(const float* __restrict__ a) {
    __shared__ int cnts[1024];
    int t = threadIdx.x;
    float s  = g_scale;
    float s2 = s * s;
    float a0 = a[D_DIM], a1 = a[D_DIM + 1], a2 = a[D_DIM + 2],
          a3 = a[D_DIM + 3], a4 = a[D_DIM + 4];
    int qb = g_qbucket;

    unsigned mask = 0u;
#pragma unroll 4
    for (int r = 0; r < 32; r++) {
        int i = (t << 5) | r;
        float n2  = s2 * g_sumsq[i];
        float acc = s * g_wa[i];
        float p = n2;              acc += p * a0;
        p *= p;                    acc += p * a1;
        p *= p;                    acc += p * a2;
        p *= p;                    acc += p * a3;
        p *= p;                    acc += p * a4;
        float h = floorf(acc * 0.25f);
        int b = (int)((long long)h % 64); if (b < 0) b += 64;
        if (b == qb) mask |= (1u << r);
    }
    int lc = __popc(mask);
    cnts[t] = lc;
    __syncthreads();
    for (int off = 1; off < 1024; off <<= 1) {
        int v = (t >= off) ? cnts[t - off] : 0;
        __syncthreads();
        cnts[t] += v;
        __syncthreads();
    }
    int off = cnts[t] - lc;
    for (int r = 0; r < 32; r++) {
        if ((mask >> r) & 1u) g_active[off++] = (t << 5) | r;
    }
    if (t == 1023) g_count = cnts[1023];
}

// ================= single-pass f16 mma.sync compacted GEMM =================
// BM=128, BN=256, BK=64, 8 warps (2x4), warp tile 64x64
#define BM 128
#define BN 256
#define BK 64
#define NCHUNK (D_DIM / BK)
#define NSTAGE 3
#define ROWB   144                      // 64 f16 = 128B data + 16B pad
#define A_TILE_B (128 * ROWB)           // 18432 B
#define B_TILE_B (256 * ROWB)           // 36864 B
#define STAGE_B (A_TILE_B + B_TILE_B)   // 55296 B
#define GEMM_SMEM (1024 + NSTAGE * STAGE_B)

__device__ __forceinline__ void load_stage(uint32_t sbase, const int* acts_s,
                                           int mrow0, int k0, int tid) {
#pragma unroll
    for (int i = 0; i < 4; i++) {
        int idx = tid + i * 256;                 // 1024 cpa16 for X tile (128 rows x 8)
        int r = idx >> 3, ch = idx & 7;
        size_t g = (size_t)(mrow0 + r) * D_DIM + k0 + ch * 8;
        cpa16(sbase + r * ROWB + ch * 16, g_xh + g);
    }
#pragma unroll
    for (int i = 0; i < 8; i++) {
        int idx = tid + i * 256;                 // 2048 cpa16 for W tile (256 rows x 8)
        int r = idx >> 3, ch = idx & 7;
        size_t g = (size_t)acts_s[r] * D_DIM + k0 + ch * 8;
        cpa16(sbase + A_TILE_B + r * ROWB + ch * 16, g_Wh + g);
    }
}

__global__ void __launch_bounds__(256, 1) k_gemm(float* __restrict__ out) {
    extern __shared__ char smem[];
    int cnt = g_count;
    int nt = blockIdx.y;
    if (nt * BN >= cnt) return;
    int mt = blockIdx.x;
    int tid = threadIdx.x;
    int lane = tid & 31, w = tid >> 5;
    int wm = w & 1, wn = w >> 1;                 // 2 x 4 warps, warp tile 64x64
    uint32_t sb = smem_u32(smem);
    int* acts_s = (int*)smem;
    {
        int j = nt * BN + tid;
        acts_s[tid] = g_active[j < cnt ? j : cnt - 1];
    }
    __syncthreads();
    int mrow0 = mt * BM;

    for (int s = 0; s < NSTAGE; s++) {
        load_stage(sb + 1024 + s * STAGE_B, acts_s, mrow0, s * BK, tid);
        CP_COMMIT();
    }

    float acc[4][8][4] = {};
    // A: rows wm*64 + mi*16 + (lane&15), k-half by lane>>4
    uint32_t a_ro = (uint32_t)(wm * 64 + (lane & 15)) * ROWB + (uint32_t)(lane >> 4) * 16;
    // B x4: 4 matrices = frags (n0,k0),(n0,k8),(n1,k0),(n1,k8)
    //   lane groups: row = ng*16 + ((lane>>4)<<3) + (lane&7), koff = ((lane>>3)&1)*16
    uint32_t b_ro = (uint32_t)(wn * 64 + ((lane >> 4) << 3) + (lane & 7)) * ROWB
                  + (uint32_t)((lane >> 3) & 1) * 16;

    int sidx = 0;
    for (int c = 0; c < NCHUNK; c++) {
        CP_WAIT2();
        __syncthreads();
        uint32_t st = sb + 1024 + sidx * STAGE_B;
#pragma unroll
        for (int ks = 0; ks < 4; ks++) {
            uint32_t ah[4][4], bq[4][4];
            uint32_t ab = st + a_ro + ks * 32;
            uint32_t bb = st + A_TILE_B + b_ro + ks * 32;
#pragma unroll
            for (int mi = 0; mi < 4; mi++)
                ldsm_x4(ah[mi], ab + mi * (16 * ROWB));
#pragma unroll
            for (int ng = 0; ng < 4; ng++)
                ldsm_x4(bq[ng], bb + ng * (16 * ROWB));
#pragma unroll
            for (int mi = 0; mi < 4; mi++)
#pragma unroll
                for (int ng = 0; ng < 4; ng++) {
                    mma_f16(acc[mi][2 * ng + 0], ah[mi], &bq[ng][0]);
                    mma_f16(acc[mi][2 * ng + 1], ah[mi], &bq[ng][2]);
                }
        }
        __syncthreads();
        int nc = c + NSTAGE;
        if (nc < NCHUNK)
            load_stage(sb + 1024 + sidx * STAGE_B, acts_s, mrow0, nc * BK, tid);
        CP_COMMIT();
        sidx = (sidx + 1 == NSTAGE) ? 0 : sidx + 1;
    }

    // epilogue: scatter to out[row][acts[j]]
    int lim = cnt - nt * BN; if (lim > BN) lim = BN;
#pragma unroll
    for (int mi = 0; mi < 4; mi++) {
        int r0 = mrow0 + wm * 64 + mi * 16 + (lane >> 2);
        float* o0 = out + (size_t)r0 * N_ROWS;
        float* o1 = o0 + (size_t)8 * N_ROWS;
#pragma unroll
        for (int ni = 0; ni < 8; ni++) {
            int jl = wn * 64 + ni * 8 + (lane & 3) * 2;
            if (jl < lim) {
                int cx = acts_s[jl];
                o0[cx] = acc[mi][ni][0];
                o1[cx] = acc[mi][ni][2];
            }
            if (jl + 1 < lim) {
                int cx = acts_s[jl + 1];
                o0[cx] = acc[mi][ni][1];
                o1[cx] = acc[mi][ni][3];
            }
        }
    }
}

// ---------------- launch ----------------
extern "C" void kernel_launch(void* const* d_in, const int* in_sizes, int n_in,
                              void* d_out, int out_size) {
    const float* x = (const float*)d_in[0];   // [2048, 2048]
    const float* W = (const float*)d_in[1];   // [32768, 2048]
    const float* a = (const float*)d_in[2];   // [2053]
    float* out = (float*)d_out;               // [2048, 32768]

    cudaFuncSetAttribute(k_gemm, cudaFuncAttributeMaxDynamicSharedMemorySize, GEMM_SMEM);

    k_init<<<1, 1>>>();
    k_rowstats<<<N_ROWS, 256>>>(W, a);
    k_convx<<<(B_DIM * D_DIM / 4) / 256, 256>>>(x);
    dim3 csg(D_DIM / 256, 16);
    k_colsum1<<<csg, 256>>>(x);
    k_colsum2<<<D_DIM / 256, 256>>>();
    k_qhash<<<1, 256>>>(a);
    k_scan<<<1, 1024>>>(a);

    cudaMemsetAsync(d_out, 0, (size_t)out_size * sizeof(float));

    dim3 grid(B_DIM / BM, N_ROWS / BN);   // mt fast -> W tile L2 reuse
    k_gemm<<<grid, 256, GEMM_SMEM>>>(out);
}

// round 6
// speedup vs baseline: 8.3885x; 1.2328x over previous
#include <cuda_runtime.h>
#include <cuda_fp16.h>
#include <cstdint>

#define N_ROWS 32768
#define D_DIM  2048
#define B_DIM  2048

// ---------------- device scratch ----------------
__device__ float g_sumsq[N_ROWS];
__device__ float g_wa[N_ROWS];
__device__ float g_part[16 * D_DIM];
__device__ float g_colsum[D_DIM];
__device__ int   g_active[N_ROWS];
__device__ int   g_count;
__device__ int   g_maxbits;
__device__ int   g_qbucket;
__device__ float g_scale;
__device__ __half g_Wh[(size_t)N_ROWS * D_DIM];   // 64 MB
__device__ __half g_xh[(size_t)B_DIM * D_DIM];    // 8 MB

// ---------------- PTX helpers (baseline ISA only) ----------------
__device__ __forceinline__ uint32_t smem_u32(const void* p) {
    uint32_t a;
    asm("{ .reg .u64 t; cvta.to.shared.u64 t, %1; cvt.u32.u64 %0, t; }" : "=r"(a) : "l"(p));
    return a;
}
__device__ __forceinline__ void cpa16(uint32_t saddr, const void* g) {
    asm volatile("cp.async.cg.shared.global [%0], [%1], 16;" :: "r"(saddr), "l"(g));
}
#define CP_COMMIT() asm volatile("cp.async.commit_group;" ::: "memory")
#define CP_WAIT2()  asm volatile("cp.async.wait_group 2;" ::: "memory")

__device__ __forceinline__ void ldsm_x4(uint32_t* r, uint32_t addr) {
    asm volatile("ldmatrix.sync.aligned.m8n8.x4.shared.b16 {%0,%1,%2,%3}, [%4];"
        : "=r"(r[0]), "=r"(r[1]), "=r"(r[2]), "=r"(r[3]) : "r"(addr));
}
__device__ __forceinline__ void mma_f16(float* c, const uint32_t* a, const uint32_t* b) {
    asm volatile("mma.sync.aligned.m16n8k16.row.col.f32.f16.f16.f32 "
        "{%0,%1,%2,%3}, {%4,%5,%6,%7}, {%8,%9}, {%0,%1,%2,%3};"
        : "+f"(c[0]), "+f"(c[1]), "+f"(c[2]), "+f"(c[3])
        : "r"(a[0]), "r"(a[1]), "r"(a[2]), "r"(a[3]), "r"(b[0]), "r"(b[1]));
}

// ---------------- init ----------------
__global__ void k_init() { g_count = 0; g_maxbits = 0; }

// -------- per-row stats + W -> f16 --------
__global__ __launch_bounds__(256) void k_rowstats(const float* __restrict__ W,
                                                  const float* __restrict__ a) {
    int row = blockIdx.x;
    int tid = threadIdx.x;
    const float4* wr = reinterpret_cast<const float4*>(W + (size_t)row * D_DIM);
    const float4* a4 = reinterpret_cast<const float4*>(a);
    __half2* wh = reinterpret_cast<__half2*>(g_Wh + (size_t)row * D_DIM);

    float ss = 0.f, wa = 0.f;
#pragma unroll
    for (int i = 0; i < 2; i++) {
        int idx = tid + i * 256;            // 512 float4 per row
        float4 w  = wr[idx];
        float4 av = __ldg(&a4[idx]);
        ss += w.x * w.x + w.y * w.y + w.z * w.z + w.w * w.w;
        wa += w.x * av.x + w.y * av.y + w.z * av.z + w.w * av.w;
        wh[idx * 2 + 0] = __floats2half2_rn(w.x, w.y);
        wh[idx * 2 + 1] = __floats2half2_rn(w.z, w.w);
    }
    for (int o = 16; o; o >>= 1) {
        ss += __shfl_down_sync(0xFFFFFFFFu, ss, o);
        wa += __shfl_down_sync(0xFFFFFFFFu, wa, o);
    }
    __shared__ float sss[8], swa[8];
    int wid = tid >> 5, lane = tid & 31;
    if (lane == 0) { sss[wid] = ss; swa[wid] = wa; }
    __syncthreads();
    if (tid == 0) {
        double S = 0.0, A = 0.0;
#pragma unroll
        for (int i = 0; i < 8; i++) { S += sss[i]; A += swa[i]; }
        float Sf = (float)S;
        g_sumsq[row] = Sf;
        g_wa[row]    = (float)A;
        atomicMax(&g_maxbits, __float_as_int(Sf));
    }
}

// -------- x -> f16 --------
__global__ __launch_bounds__(256) void k_convx(const float* __restrict__ x) {
    int i = blockIdx.x * 256 + threadIdx.x;
    float4 v = reinterpret_cast<const float4*>(x)[i];
    __half2* xh = reinterpret_cast<__half2*>(g_xh);
    xh[i * 2 + 0] = __floats2half2_rn(v.x, v.y);
    xh[i * 2 + 1] = __floats2half2_rn(v.z, v.w);
}

// -------- column sums of x: stage 1 (deterministic partials) --------
__global__ __launch_bounds__(256) void k_colsum1(const float* __restrict__ x) {
    int d = blockIdx.x * 256 + threadIdx.x;
    int p = blockIdx.y;                       // 16 row-partitions of 128 rows
    const float* xp = x + (size_t)p * 128 * D_DIM + d;
    float s0 = 0.f, s1 = 0.f;
    for (int b = 0; b < 128; b += 2) {
        s0 += xp[(size_t)b * D_DIM];
        s1 += xp[(size_t)(b + 1) * D_DIM];
    }
    g_part[p * D_DIM + d] = s0 + s1;
}
// -------- stage 2: fixed-order combine --------
__global__ __launch_bounds__(256) void k_colsum2() {
    int d = blockIdx.x * 256 + threadIdx.x;
    double s = 0.0;
#pragma unroll
    for (int p = 0; p < 16; p++) s += (double)g_part[p * D_DIM + d];
    g_colsum[d] = (float)s;
}

// -------- q bucket + scale --------
__global__ __launch_bounds__(256) void k_qhash(const float* __restrict__ a) {
    __shared__ double s_n2[256], s_ca[256];
    int t = threadIdx.x;
    double n2 = 0.0, ca = 0.0;
    for (int d = t; d < D_DIM; d += 256) {
        float c = g_colsum[d];
        n2 += (double)c * (double)c;
        ca += (double)c * (double)a[d];
    }
    s_n2[t] = n2; s_ca[t] = ca;
    __syncthreads();
    for (int off = 128; off; off >>= 1) {
        if (t < off) { s_n2[t] += s_n2[t + off]; s_ca[t] += s_ca[t + off]; }
        __syncthreads();
    }
    if (t == 0) {
        float nrm = sqrtf((float)s_n2[0]);
        float qd  = (float)s_ca[0] / nrm;
        float tail = a[D_DIM] + a[D_DIM + 1] + a[D_DIM + 2] + a[D_DIM + 3] + a[D_DIM + 4];
        float acc = qd + 0.5f * tail;
        float h = floorf(acc * 0.25f);
        long long hi = (long long)h;
        int b = (int)(hi % 64); if (b < 0) b += 64;
        g_qbucket = b;
        g_scale = 0.83f / sqrtf(__int_as_float(g_maxbits));
    }
}

// -------- mask + deterministic sorted compaction --------
__global__ __launch_bounds__(1024) void k_scan(const float* __restrict__ a) {
    __shared__ int cnts[1024];
    int t = threadIdx.x;
    float s  = g_scale;
    float s2 = s * s;
    float a0 = a[D_DIM], a1 = a[D_DIM + 1], a2 = a[D_DIM + 2],
          a3 = a[D_DIM + 3], a4 = a[D_DIM + 4];
    int qb = g_qbucket;

    unsigned mask = 0u;
#pragma unroll 4
    for (int r = 0; r < 32; r++) {
        int i = (t << 5) | r;
        float n2  = s2 * g_sumsq[i];
        float acc = s * g_wa[i];
        float p = n2;              acc += p * a0;
        p *= p;                    acc += p * a1;
        p *= p;                    acc += p * a2;
        p *= p;                    acc += p * a3;
        p *= p;                    acc += p * a4;
        float h = floorf(acc * 0.25f);
        int b = (int)((long long)h % 64); if (b < 0) b += 64;
        if (b == qb) mask |= (1u << r);
    }
    int lc = __popc(mask);
    cnts[t] = lc;
    __syncthreads();
    for (int off = 1; off < 1024; off <<= 1) {
        int v = (t >= off) ? cnts[t - off] : 0;
        __syncthreads();
        cnts[t] += v;
        __syncthreads();
    }
    int off = cnts[t] - lc;
    for (int r = 0; r < 32; r++) {
        if ((mask >> r) & 1u) g_active[off++] = (t << 5) | r;
    }
    if (t == 1023) g_count = cnts[1023];
}

// ================= single-pass f16 mma.sync compacted GEMM =================
// 128 threads (2x2 warps), CTA tile 128x128, warp tile 64x64, BK=64
// smem/CTA = 109 KB -> 2 CTAs per SM
#define BM 128
#define BN 128
#define BK 64
#define NCHUNK (D_DIM / BK)
#define NSTAGE 3
#define ROWB   144                      // 64 f16 = 128B data + 16B pad
#define A_TILE_B (128 * ROWB)           // 18432 B
#define B_TILE_B (128 * ROWB)           // 18432 B
#define STAGE_B (A_TILE_B + B_TILE_B)   // 36864 B
#define GEMM_SMEM (1024 + NSTAGE * STAGE_B)

__device__ __forceinline__ void load_stage(uint32_t sbase, const int* acts_s,
                                           int mrow0, int k0, int tid) {
#pragma unroll
    for (int i = 0; i < 8; i++) {
        int idx = tid + i * 128;                 // 1024 cpa16 for X tile (128 rows x 8)
        int r = idx >> 3, ch = idx & 7;
        size_t g = (size_t)(mrow0 + r) * D_DIM + k0 + ch * 8;
        cpa16(sbase + r * ROWB + ch * 16, g_xh + g);
    }
#pragma unroll
    for (int i = 0; i < 8; i++) {
        int idx = tid + i * 128;                 // 1024 cpa16 for W tile (128 rows x 8)
        int r = idx >> 3, ch = idx & 7;
        size_t g = (size_t)acts_s[r] * D_DIM + k0 + ch * 8;
        cpa16(sbase + A_TILE_B + r * ROWB + ch * 16, g_Wh + g);
    }
}

__global__ void __launch_bounds__(128, 2) k_gemm(float* __restrict__ out) {
    extern __shared__ char smem[];
    int cnt = g_count;
    int nt = blockIdx.y;
    if (nt * BN >= cnt) return;
    int mt = blockIdx.x;
    int tid = threadIdx.x;
    int lane = tid & 31, w = tid >> 5;
    int wm = w & 1, wn = w >> 1;                 // 2 x 2 warps, warp tile 64x64
    uint32_t sb = smem_u32(smem);
    int* acts_s = (int*)smem;
    {
        int j = nt * BN + tid;
        acts_s[tid] = g_active[j < cnt ? j : cnt - 1];
    }
    __syncthreads();
    int mrow0 = mt * BM;

    for (int s = 0; s < NSTAGE; s++) {
        load_stage(sb + 1024 + s * STAGE_B, acts_s, mrow0, s * BK, tid);
        CP_COMMIT();
    }

    float acc[4][8][4] = {};
    // A: rows wm*64 + mi*16 + (lane&15), k-half by lane>>4
    uint32_t a_ro = (uint32_t)(wm * 64 + (lane & 15)) * ROWB + (uint32_t)(lane >> 4) * 16;
    // B x4: frags (n0,k0),(n0,k8),(n1,k0),(n1,k8)
    uint32_t b_ro = (uint32_t)(wn * 64 + ((lane >> 4) << 3) + (lane & 7)) * ROWB
                  + (uint32_t)((lane >> 3) & 1) * 16;

    int sidx = 0;
    for (int c = 0; c < NCHUNK; c++) {
        CP_WAIT2();
        __syncthreads();
        uint32_t st = sb + 1024 + sidx * STAGE_B;
#pragma unroll
        for (int ks = 0; ks < 4; ks++) {
            uint32_t ah[4][4], bq[4][4];
            uint32_t ab = st + a_ro + ks * 32;
            uint32_t bb = st + A_TILE_B + b_ro + ks * 32;
#pragma unroll
            for (int mi = 0; mi < 4; mi++)
                ldsm_x4(ah[mi], ab + mi * (16 * ROWB));
#pragma unroll
            for (int ng = 0; ng < 4; ng++)
                ldsm_x4(bq[ng], bb + ng * (16 * ROWB));
#pragma unroll
            for (int mi = 0; mi < 4; mi++)
#pragma unroll
                for (int ng = 0; ng < 4; ng++) {
                    mma_f16(acc[mi][2 * ng + 0], ah[mi], &bq[ng][0]);
                    mma_f16(acc[mi][2 * ng + 1], ah[mi], &bq[ng][2]);
                }
        }
        __syncthreads();
        int nc = c + NSTAGE;
        if (nc < NCHUNK)
            load_stage(sb + 1024 + sidx * STAGE_B, acts_s, mrow0, nc * BK, tid);
        CP_COMMIT();
        sidx = (sidx + 1 == NSTAGE) ? 0 : sidx + 1;
    }

    // epilogue: scatter to out[row][acts[j]]
    int lim = cnt - nt * BN; if (lim > BN) lim = BN;
#pragma unroll
    for (int mi = 0; mi < 4; mi++) {
        int r0 = mrow0 + wm * 64 + mi * 16 + (lane >> 2);
        float* o0 = out + (size_t)r0 * N_ROWS;
        float* o1 = o0 + (size_t)8 * N_ROWS;
#pragma unroll
        for (int ni = 0; ni < 8; ni++) {
            int jl = wn * 64 + ni * 8 + (lane & 3) * 2;
            if (jl < lim) {
                int cx = acts_s[jl];
                o0[cx] = acc[mi][ni][0];
                o1[cx] = acc[mi][ni][2];
            }
            if (jl + 1 < lim) {
                int cx = acts_s[jl + 1];
                o0[cx] = acc[mi][ni][1];
                o1[cx] = acc[mi][ni][3];
            }
        }
    }
}

// ---------------- launch ----------------
extern "C" void kernel_launch(void* const* d_in, const int* in_sizes, int n_in,
                              void* d_out, int out_size) {
    const float* x = (const float*)d_in[0];   // [2048, 2048]
    const float* W = (const float*)d_in[1];   // [32768, 2048]
    const float* a = (const float*)d_in[2];   // [2053]
    float* out = (float*)d_out;               // [2048, 32768]

    cudaFuncSetAttribute(k_gemm, cudaFuncAttributeMaxDynamicSharedMemorySize, GEMM_SMEM);

    k_init<<<1, 1>>>();
    k_rowstats<<<N_ROWS, 256>>>(W, a);
    k_convx<<<(B_DIM * D_DIM / 4) / 256, 256>>>(x);
    dim3 csg(D_DIM / 256, 16);
    k_colsum1<<<csg, 256>>>(x);
    k_colsum2<<<D_DIM / 256, 256>>>();
    k_qhash<<<1, 256>>>(a);
    k_scan<<<1, 1024>>>(a);

    cudaMemsetAsync(d_out, 0, (size_t)out_size * sizeof(float));

    dim3 grid(B_DIM / BM, N_ROWS / BN);   // mt fast -> W tile L2 reuse
    k_gemm<<<grid, 128, GEMM_SMEM>>>(out);
}